// round 13
// baseline (speedup 1.0000x reference)
#include <cuda_runtime.h>
#include <cuda_bf16.h>

// HMM forward, scaled probability domain.
//   w_t[j] = (sum_i w_{t-1}[i] * exp(trans[i,j])) * inv_norm * exp(emit[j,obs[t]])
//   out    = log(sum_j w_final[j]) + sum log(norm)
//
// R12: distributed epoch flags (grid.sync idiom) + warp-owns-columns GEMV.
//  - 64 persistent CTAs x 256 threads (8 warps); CTA owns 16 columns,
//    each warp computes 2 FULL columns from all 1024 sources:
//    no cross-warp reduction, no finalize stage, rescale is warp-local.
//  - Sync: per-CTA epoch flag on its own 128B line. Writer side:
//    stores -> __syncthreads -> (one thread) fence.acq_rel.gpu -> relaxed
//    flag store. Reader side: poller warp reads all 64 flags in parallel
//    (relaxed, 2/lane) until all >= t, then one fence.acq_rel.gpu
//    (CCTL.IVALL -> L1 invalidated -> plain w loads are coherent), then bar.
//    This is exactly the cooperative-groups grid.sync protocol, minus its
//    generality. No atomic-unit serialization, no single hot line.

#define S     1024
#define NOBS  4096
#define TT    8192
#define KCTA  64
#define CCOL  16
#define NTHR  256
#define NWARP 8

__device__ __align__(16) float    g_emitT[TT * S];   // exp(emit[j, obs[t]]), [t][j]
__device__ __align__(16) float    g_w[2][S];         // double-buffered state vector
__device__ __align__(128) unsigned g_flags[KCTA][32]; // one 128B line per CTA

__device__ __forceinline__ void fence_acqrel_gpu() {
    asm volatile("fence.acq_rel.gpu;" ::: "memory");
}
__device__ __forceinline__ void st_rlx_u32(unsigned* p, unsigned v) {
    asm volatile("st.relaxed.gpu.global.u32 [%0], %1;" :: "l"(p), "r"(v) : "memory");
}
__device__ __forceinline__ unsigned ld_rlx_u32(const unsigned* p) {
    unsigned v;
    asm volatile("ld.relaxed.gpu.global.u32 %0, [%1];" : "=r"(v) : "l"(p) : "memory");
    return v;
}

// Prologue: gather exp(emit) per timestep, init w0, reset flags (every replay).
__global__ void hmm_init_kernel(const int* __restrict__ obs,
                                const float* __restrict__ start,
                                const float* __restrict__ emit) {
    long idx = (long)blockIdx.x * blockDim.x + threadIdx.x;
    if (idx < KCTA * 32) ((unsigned*)g_flags)[idx] = 0u;
    if (idx >= (long)TT * S) return;
    int t = (int)(idx >> 10);
    int j = (int)(idx & (S - 1));
    float e = expf(emit[(long)j * NOBS + obs[t]]);
    g_emitT[idx] = e;
    if (t == 0) g_w[0][j] = expf(start[j]) * e;
}

__global__ void __launch_bounds__(NTHR, 1)
hmm_main_kernel(const float* __restrict__ trans, float* __restrict__ out) {
    const int tid  = threadIdx.x;
    const int lane = tid & 31;
    const int wid  = tid >> 5;
    const int cta  = blockIdx.x;
    const int col0 = cta * CCOL + (wid << 1);   // this warp's 2 output columns

    // P slices in registers: P0/P1[4k+u] = exp(trans[128k + 4*lane + u][col]).
    float P0[32], P1[32];
    #pragma unroll
    for (int k = 0; k < 8; ++k) {
        #pragma unroll
        for (int u = 0; u < 4; ++u) {
            int row = (k << 7) + (lane << 2) + u;
            P0[(k << 2) + u] = expf(__ldg(&trans[(long)row * S + col0]));
            P1[(k << 2) + u] = expf(__ldg(&trans[(long)row * S + col0 + 1]));
        }
    }

    // Emission values for storer lanes (lane 0 -> col0, lane 1 -> col0+1).
    float e_c = 0.0f, e_n = 0.0f, e_n2 = 0.0f;
    if (lane < 2) {
        e_c = __ldg(&g_emitT[1 * S + col0 + lane]);
        e_n = __ldg(&g_emitT[2 * S + col0 + lane]);
    }

    float logscale = 0.0f;   // identical across ALL threads (warp-local rescale)

    for (int t = 1; t < TT; ++t) {
        const int  rb   = (t - 1) & 1;
        const bool resc = ((t - 1) & 7) == 0;

        // ---- Load the full w vector: 8 coalesced float4 per lane (L2) ----
        float4 wv0 = *reinterpret_cast<const float4*>(&g_w[rb][(0 << 7) + (lane << 2)]);
        float4 wv1 = *reinterpret_cast<const float4*>(&g_w[rb][(1 << 7) + (lane << 2)]);
        float4 wv2 = *reinterpret_cast<const float4*>(&g_w[rb][(2 << 7) + (lane << 2)]);
        float4 wv3 = *reinterpret_cast<const float4*>(&g_w[rb][(3 << 7) + (lane << 2)]);
        float4 wv4 = *reinterpret_cast<const float4*>(&g_w[rb][(4 << 7) + (lane << 2)]);
        float4 wv5 = *reinterpret_cast<const float4*>(&g_w[rb][(5 << 7) + (lane << 2)]);
        float4 wv6 = *reinterpret_cast<const float4*>(&g_w[rb][(6 << 7) + (lane << 2)]);
        float4 wv7 = *reinterpret_cast<const float4*>(&g_w[rb][(7 << 7) + (lane << 2)]);

        // Emission prefetch, two steps deep.
        if (lane < 2) {
            int tn = (t + 2 < TT) ? t + 2 : TT - 1;
            e_n2 = __ldg(&g_emitT[tn * S + col0 + lane]);
        }

        // ---- Warp-local rescale (every 8th step): warp holds the full vector ----
        float inv = 1.0f;
        if (resc) {
            float m = fmaxf(fmaxf(wv0.x, wv0.y), fmaxf(wv0.z, wv0.w));
            m = fmaxf(m, fmaxf(fmaxf(wv1.x, wv1.y), fmaxf(wv1.z, wv1.w)));
            m = fmaxf(m, fmaxf(fmaxf(wv2.x, wv2.y), fmaxf(wv2.z, wv2.w)));
            m = fmaxf(m, fmaxf(fmaxf(wv3.x, wv3.y), fmaxf(wv3.z, wv3.w)));
            m = fmaxf(m, fmaxf(fmaxf(wv4.x, wv4.y), fmaxf(wv4.z, wv4.w)));
            m = fmaxf(m, fmaxf(fmaxf(wv5.x, wv5.y), fmaxf(wv5.z, wv5.w)));
            m = fmaxf(m, fmaxf(fmaxf(wv6.x, wv6.y), fmaxf(wv6.z, wv6.w)));
            m = fmaxf(m, fmaxf(fmaxf(wv7.x, wv7.y), fmaxf(wv7.z, wv7.w)));
            #pragma unroll
            for (int off = 16; off; off >>= 1)
                m = fmaxf(m, __shfl_xor_sync(0xffffffffu, m, off));
            inv = 1.0f / m;
            logscale += logf(m);
        }

        // ---- GEMV: 2 full columns, 64 FFMA, 4 chains, 10 SHFL total ----
        float a0, b0, a1, b1;
        a0 = wv0.x * P0[0]  + wv0.y * P0[1];   b0 = wv0.z * P0[2]  + wv0.w * P0[3];
        a1 = wv0.x * P1[0]  + wv0.y * P1[1];   b1 = wv0.z * P1[2]  + wv0.w * P1[3];
        a0 += wv1.x * P0[4]  + wv1.y * P0[5];  b0 += wv1.z * P0[6]  + wv1.w * P0[7];
        a1 += wv1.x * P1[4]  + wv1.y * P1[5];  b1 += wv1.z * P1[6]  + wv1.w * P1[7];
        a0 += wv2.x * P0[8]  + wv2.y * P0[9];  b0 += wv2.z * P0[10] + wv2.w * P0[11];
        a1 += wv2.x * P1[8]  + wv2.y * P1[9];  b1 += wv2.z * P1[10] + wv2.w * P1[11];
        a0 += wv3.x * P0[12] + wv3.y * P0[13]; b0 += wv3.z * P0[14] + wv3.w * P0[15];
        a1 += wv3.x * P1[12] + wv3.y * P1[13]; b1 += wv3.z * P1[14] + wv3.w * P1[15];
        a0 += wv4.x * P0[16] + wv4.y * P0[17]; b0 += wv4.z * P0[18] + wv4.w * P0[19];
        a1 += wv4.x * P1[16] + wv4.y * P1[17]; b1 += wv4.z * P1[18] + wv4.w * P1[19];
        a0 += wv5.x * P0[20] + wv5.y * P0[21]; b0 += wv5.z * P0[22] + wv5.w * P0[23];
        a1 += wv5.x * P1[20] + wv5.y * P1[21]; b1 += wv5.z * P1[22] + wv5.w * P1[23];
        a0 += wv6.x * P0[24] + wv6.y * P0[25]; b0 += wv6.z * P0[26] + wv6.w * P0[27];
        a1 += wv6.x * P1[24] + wv6.y * P1[25]; b1 += wv6.z * P1[26] + wv6.w * P1[27];
        a0 += wv7.x * P0[28] + wv7.y * P0[29]; b0 += wv7.z * P0[30] + wv7.w * P0[31];
        a1 += wv7.x * P1[28] + wv7.y * P1[29]; b1 += wv7.z * P1[30] + wv7.w * P1[31];
        float s0 = a0 + b0, s1 = a1 + b1;
        #pragma unroll
        for (int off = 16; off; off >>= 1) {
            s0 += __shfl_xor_sync(0xffffffffu, s0, off);
            s1 += __shfl_xor_sync(0xffffffffu, s1, off);
        }

        // ---- Store this warp's 2 columns directly ----
        if (lane < 2) {
            float sv = (lane == 0) ? s0 : s1;
            g_w[t & 1][col0 + lane] = sv * inv * e_c;
            e_c = e_n;
            e_n = e_n2;
        }
        __syncthreads();                        // all 16 column stores done CTA-wide

        // ---- grid.sync idiom: flag release + parallel poll (warp 1) ----
        if (wid == 1) {
            if (lane == 0) {
                fence_acqrel_gpu();             // order CTA's stores at gpu scope
                st_rlx_u32(&g_flags[cta][0], (unsigned)t);
            }
            bool ok;
            do {
                unsigned f0 = ld_rlx_u32(&g_flags[lane][0]);
                unsigned f1 = ld_rlx_u32(&g_flags[lane + 32][0]);
                ok = (f0 >= (unsigned)t) && (f1 >= (unsigned)t);
            } while (!__all_sync(0xffffffffu, ok));
            if (lane == 0) fence_acqrel_gpu();  // acquire: CCTL.IVALL -> L1 fresh
        }
        __syncthreads();                        // release CTA into step t+1
    }

    // ---- Epilogue: CTA 0 / warp 0 reduces the final vector ----
    if (cta == 0 && wid == 0) {
        const int fb = (TT - 1) & 1;
        float s = 0.0f;
        #pragma unroll
        for (int k = 0; k < 8; ++k) {
            float4 v = *reinterpret_cast<const float4*>(&g_w[fb][(k << 7) + (lane << 2)]);
            s += v.x + v.y + v.z + v.w;
        }
        #pragma unroll
        for (int off = 16; off; off >>= 1)
            s += __shfl_xor_sync(0xffffffffu, s, off);
        if (lane == 0) out[0] = logf(s) + logscale;
    }
}

extern "C" void kernel_launch(void* const* d_in, const int* in_sizes, int n_in,
                              void* d_out, int out_size) {
    const int*   obs   = (const int*)d_in[0];
    const float* start = (const float*)d_in[1];
    const float* trans = (const float*)d_in[2];
    const float* emit  = (const float*)d_in[3];
    float*       out   = (float*)d_out;

    (void)in_sizes; (void)n_in; (void)out_size;

    const int init_blocks = (TT * S + 255) / 256;
    hmm_init_kernel<<<init_blocks, 256>>>(obs, start, emit);
    hmm_main_kernel<<<KCTA, NTHR>>>(trans, out);
}